// round 15
// baseline (speedup 1.0000x reference)
#include <cuda_runtime.h>
#include <cuda_bf16.h>
#include <math.h>

#define HD 128
#define NMAX 1048576
#define GMAX 4608
#define WSTRIDE 136   // padded row stride (bf16 elems) for conflict-free B-frag loads

// ---------------- scratch (device globals; no allocation allowed) ----------------
__device__ float g_s[NMAX];                 // per-row attention logits
__device__ int   g_seg[GMAX + 1];           // segment boundaries
__device__ __nv_bfloat16 g_w1hi[HD * HD];   // w1^T split hi (layout [n][k])
__device__ __nv_bfloat16 g_w1lo[HD * HD];   // w1^T split lo

// ---------------- K0: split + transpose w1 into bf16 hi/lo ----------------
__global__ void prep_w1_kernel(const float* __restrict__ w1) {
    int idx = blockIdx.x * blockDim.x + threadIdx.x;
    if (idx < HD * HD) {
        int k = idx >> 7, n = idx & 127;           // w1 is [k][n] row-major
        float v = w1[idx];
        __nv_bfloat16 hi = __float2bfloat16(v);
        float r = v - __bfloat162float(hi);
        g_w1hi[n * HD + k] = hi;                   // store transposed: [n][k]
        g_w1lo[n * HD + k] = __float2bfloat16(r);
    }
}

// ---------------- K2: segment boundaries (binary search over sorted batch) ----------------
// batch may be int64 or int32 depending on environment; detect at runtime by
// probing odd int32 positions in the first half of the buffer (safe under both
// interpretations): under int64 these are high words of small values -> 0;
// under int32 they are batch values at rows >= N/4 -> >= ~1000.
__global__ void seg_kernel(const void* __restrict__ batch_raw, int n, int G) {
    const int* v32 = (const int*)batch_raw;
    bool is64 = (v32[(n / 2) | 1] == 0) && (v32[(n / 4) | 1] == 0) && (v32[(n / 3) | 1] == 0);
    int gg = blockIdx.x * blockDim.x + threadIdx.x;
    if (gg > G) return;
    long long key = (long long)gg;
    int lo = 0, hi = n;
    const long long* v64 = (const long long*)batch_raw;
    while (lo < hi) {
        int mid = (lo + hi) >> 1;
        long long bv = is64 ? v64[mid] : (long long)v32[mid];
        if (bv < key) lo = mid + 1; else hi = mid;
    }
    g_seg[gg] = lo;
}

// ---------------- K1: score kernel (bf16x3 tensor-core MLP) ----------------
__device__ __forceinline__ unsigned split_pack(float2 p, unsigned& lo) {
    __nv_bfloat16 h0 = __float2bfloat16(p.x);
    __nv_bfloat16 h1 = __float2bfloat16(p.y);
    __nv_bfloat16 l0 = __float2bfloat16(p.x - __bfloat162float(h0));
    __nv_bfloat16 l1 = __float2bfloat16(p.y - __bfloat162float(h1));
    __nv_bfloat162 L = __halves2bfloat162(l0, l1);
    lo = *reinterpret_cast<unsigned*>(&L);
    __nv_bfloat162 Hh = __halves2bfloat162(h0, h1);
    return *reinterpret_cast<unsigned*>(&Hh);
}

__device__ __forceinline__ void mma16816(float* c, const unsigned* a, unsigned b0, unsigned b1) {
    asm volatile(
        "mma.sync.aligned.m16n8k16.row.col.f32.bf16.bf16.f32 "
        "{%0,%1,%2,%3},{%4,%5,%6,%7},{%8,%9},{%0,%1,%2,%3};\n"
        : "+f"(c[0]), "+f"(c[1]), "+f"(c[2]), "+f"(c[3])
        : "r"(a[0]), "r"(a[1]), "r"(a[2]), "r"(a[3]), "r"(b0), "r"(b1));
}

__global__ void __launch_bounds__(256, 2) score_kernel(
    const float* __restrict__ x, const float* __restrict__ b1,
    const float* __restrict__ w2, const float* __restrict__ b2,
    int nrows, int ntiles)
{
    extern __shared__ unsigned char smem_raw[];
    __nv_bfloat16* whi = (__nv_bfloat16*)smem_raw;          // [128][136]
    __nv_bfloat16* wlo = whi + HD * WSTRIDE;                // [128][136]
    float* sb1 = (float*)(wlo + HD * WSTRIDE);
    float* sw2 = sb1 + HD;

    for (int idx = threadIdx.x; idx < HD * HD; idx += blockDim.x) {
        int n = idx >> 7, k = idx & 127;
        whi[n * WSTRIDE + k] = g_w1hi[idx];
        wlo[n * WSTRIDE + k] = g_w1lo[idx];
    }
    if (threadIdx.x < HD) {
        sb1[threadIdx.x] = b1[threadIdx.x];
        sw2[threadIdx.x] = w2[threadIdx.x];
    }
    __syncthreads();

    float bias2 = b2[0];
    int warp = threadIdx.x >> 5, lane = threadIdx.x & 31;
    int g = lane >> 2, t = lane & 3;

    for (int tile = blockIdx.x; tile < ntiles; tile += gridDim.x) {
        int rbase = tile * 128 + warp * 16;
        int r0 = rbase + g, r1 = rbase + g + 8;
        bool ok0 = r0 < nrows, ok1 = r1 < nrows;
        const float* xr0 = x + (size_t)r0 * HD;
        const float* xr1 = x + (size_t)r1 * HD;

        float acc[16][4];
        #pragma unroll
        for (int j = 0; j < 16; j++) { acc[j][0] = 0.f; acc[j][1] = 0.f; acc[j][2] = 0.f; acc[j][3] = 0.f; }

        #pragma unroll
        for (int k0 = 0; k0 < 8; k0++) {
            int c0 = k0 * 16 + 2 * t;
            unsigned ah[4], al[4];
            float2 p;
            p = ok0 ? *(const float2*)(xr0 + c0)     : make_float2(0.f, 0.f);
            ah[0] = split_pack(p, al[0]);
            p = ok1 ? *(const float2*)(xr1 + c0)     : make_float2(0.f, 0.f);
            ah[1] = split_pack(p, al[1]);
            p = ok0 ? *(const float2*)(xr0 + c0 + 8) : make_float2(0.f, 0.f);
            ah[2] = split_pack(p, al[2]);
            p = ok1 ? *(const float2*)(xr1 + c0 + 8) : make_float2(0.f, 0.f);
            ah[3] = split_pack(p, al[3]);

            #pragma unroll
            for (int j = 0; j < 16; j++) {
                const __nv_bfloat16* bh = whi + (j * 8 + g) * WSTRIDE + c0;
                const __nv_bfloat16* bl = wlo + (j * 8 + g) * WSTRIDE + c0;
                unsigned bh0 = *(const unsigned*)bh;
                unsigned bh1 = *(const unsigned*)(bh + 8);
                unsigned bl0 = *(const unsigned*)bl;
                unsigned bl1 = *(const unsigned*)(bl + 8);
                mma16816(acc[j], ah, bh0, bh1);   // hi*hi
                mma16816(acc[j], ah, bl0, bl1);   // hi*lo
                mma16816(acc[j], al, bh0, bh1);   // lo*hi
            }
        }

        // epilogue: tanh + dot(w2), reduce across the 4 lanes of each row-group
        float p0 = 0.f, p1 = 0.f;
        #pragma unroll
        for (int j = 0; j < 16; j++) {
            int col0 = j * 8 + 2 * t;
            p0 += tanhf(acc[j][0] + sb1[col0])     * sw2[col0];
            p0 += tanhf(acc[j][1] + sb1[col0 + 1]) * sw2[col0 + 1];
            p1 += tanhf(acc[j][2] + sb1[col0])     * sw2[col0];
            p1 += tanhf(acc[j][3] + sb1[col0 + 1]) * sw2[col0 + 1];
        }
        p0 += __shfl_xor_sync(0xffffffffu, p0, 1);
        p0 += __shfl_xor_sync(0xffffffffu, p0, 2);
        p1 += __shfl_xor_sync(0xffffffffu, p1, 1);
        p1 += __shfl_xor_sync(0xffffffffu, p1, 2);
        if (t == 0) {
            if (ok0) g_s[r0] = p0 + bias2;
            if (ok1) g_s[r1] = p1 + bias2;
        }
    }
}

// ---------------- K3: per-graph softmax + weighted pooling ----------------
__global__ void pool_kernel(const float* __restrict__ x, float* __restrict__ out, int G) {
    __shared__ float wsm[128];
    __shared__ float red[4];
    int gidx = blockIdx.x;
    int tid = threadIdx.x;
    int s0 = g_seg[gidx], s1 = g_seg[gidx + 1];

    // max
    float m = -INFINITY;
    for (int i = s0 + tid; i < s1; i += 128) m = fmaxf(m, g_s[i]);
    #pragma unroll
    for (int o = 16; o; o >>= 1) m = fmaxf(m, __shfl_xor_sync(0xffffffffu, m, o));
    if ((tid & 31) == 0) red[tid >> 5] = m;
    __syncthreads();
    m = fmaxf(fmaxf(red[0], red[1]), fmaxf(red[2], red[3]));
    __syncthreads();

    // denom
    float ds = 0.f;
    for (int i = s0 + tid; i < s1; i += 128) ds += __expf(g_s[i] - m);
    #pragma unroll
    for (int o = 16; o; o >>= 1) ds += __shfl_xor_sync(0xffffffffu, ds, o);
    if ((tid & 31) == 0) red[tid >> 5] = ds;
    __syncthreads();
    float denom = red[0] + red[1] + red[2] + red[3];
    float inv = (s1 > s0 && denom > 0.f) ? (1.f / denom) : 0.f;

    // weighted pooling: thread tid owns column tid
    float acc = 0.f;
    for (int base = s0; base < s1; base += 128) {
        int i = base + tid;
        __syncthreads();
        wsm[tid] = (i < s1) ? (__expf(g_s[i] - m) * inv) : 0.f;
        __syncthreads();
        int cnt = min(128, s1 - base);
        const float* xp = x + (size_t)base * HD + tid;
        int j = 0;
        for (; j + 4 <= cnt; j += 4) {
            float a0 = xp[(size_t)(j + 0) * HD];
            float a1 = xp[(size_t)(j + 1) * HD];
            float a2 = xp[(size_t)(j + 2) * HD];
            float a3 = xp[(size_t)(j + 3) * HD];
            acc += wsm[j] * a0;
            acc += wsm[j + 1] * a1;
            acc += wsm[j + 2] * a2;
            acc += wsm[j + 3] * a3;
        }
        for (; j < cnt; j++) acc += wsm[j] * xp[(size_t)j * HD];
    }
    out[(size_t)gidx * HD + tid] = acc;
}

// ---------------- launch ----------------
extern "C" void kernel_launch(void* const* d_in, const int* in_sizes, int n_in,
                              void* d_out, int out_size) {
    const float* x  = (const float*)d_in[0];
    const void*  batch = d_in[1];
    const float* w1 = (const float*)d_in[2];
    const float* b1 = (const float*)d_in[3];
    const float* w2 = (const float*)d_in[4];
    const float* b2 = (const float*)d_in[5];
    float* out = (float*)d_out;

    int N = in_sizes[1];           // rows
    int G = out_size / HD;         // graphs
    int ntiles = (N + 127) / 128;

    const int SMEM = 2 * HD * WSTRIDE * (int)sizeof(__nv_bfloat16) + 2 * HD * (int)sizeof(float);
    cudaFuncSetAttribute(score_kernel, cudaFuncAttributeMaxDynamicSharedMemorySize, SMEM);

    prep_w1_kernel<<<(HD * HD + 255) / 256, 256>>>(w1);
    score_kernel<<<304, 256, SMEM>>>(x, b1, w2, b2, N, ntiles);
    seg_kernel<<<(G + 1 + 255) / 256, 256>>>(batch, N, G);
    pool_kernel<<<G, 128>>>(x, out, G);
}

// round 16
// speedup vs baseline: 1.0011x; 1.0011x over previous
#include <cuda_runtime.h>
#include <cuda_bf16.h>
#include <math.h>

#define HD 128
#define NMAX 1048576
#define GMAX 4608
#define WSTRIDE 136   // padded row stride (bf16 elems) for conflict-free B-frag loads

// ---------------- scratch (device globals; no allocation allowed) ----------------
__device__ float g_s[NMAX];                 // per-row attention logits
__device__ int   g_seg[GMAX + 1];           // segment boundaries
__device__ __nv_bfloat16 g_w1hi[HD * HD];   // w1^T split hi (layout [n][k])
__device__ __nv_bfloat16 g_w1lo[HD * HD];   // w1^T split lo

// ---------------- K0: split + transpose w1 into bf16 hi/lo ----------------
__global__ void prep_w1_kernel(const float* __restrict__ w1) {
    int idx = blockIdx.x * blockDim.x + threadIdx.x;
    if (idx < HD * HD) {
        int k = idx >> 7, n = idx & 127;           // w1 is [k][n] row-major
        float v = w1[idx];
        __nv_bfloat16 hi = __float2bfloat16(v);
        float r = v - __bfloat162float(hi);
        g_w1hi[n * HD + k] = hi;                   // store transposed: [n][k]
        g_w1lo[n * HD + k] = __float2bfloat16(r);
    }
}

// ---------------- K2: segment boundaries (binary search over sorted batch) ----------------
// batch may be int64 or int32 depending on environment; detect at runtime by
// probing odd int32 positions in the first half of the buffer (safe under both
// interpretations): under int64 these are high words of small values -> 0;
// under int32 they are batch values at rows >= N/4 -> >= ~1000.
__global__ void seg_kernel(const void* __restrict__ batch_raw, int n, int G) {
    const int* v32 = (const int*)batch_raw;
    bool is64 = (v32[(n / 2) | 1] == 0) && (v32[(n / 4) | 1] == 0) && (v32[(n / 3) | 1] == 0);
    int gg = blockIdx.x * blockDim.x + threadIdx.x;
    if (gg > G) return;
    long long key = (long long)gg;
    int lo = 0, hi = n;
    const long long* v64 = (const long long*)batch_raw;
    while (lo < hi) {
        int mid = (lo + hi) >> 1;
        long long bv = is64 ? v64[mid] : (long long)v32[mid];
        if (bv < key) lo = mid + 1; else hi = mid;
    }
    g_seg[gg] = lo;
}

// ---------------- K1: score kernel (bf16x3 tensor-core MLP) ----------------
__device__ __forceinline__ unsigned split_pack(float2 p, unsigned& lo) {
    __nv_bfloat16 h0 = __float2bfloat16(p.x);
    __nv_bfloat16 h1 = __float2bfloat16(p.y);
    __nv_bfloat16 l0 = __float2bfloat16(p.x - __bfloat162float(h0));
    __nv_bfloat16 l1 = __float2bfloat16(p.y - __bfloat162float(h1));
    __nv_bfloat162 L = __halves2bfloat162(l0, l1);
    lo = *reinterpret_cast<unsigned*>(&L);
    __nv_bfloat162 Hh = __halves2bfloat162(h0, h1);
    return *reinterpret_cast<unsigned*>(&Hh);
}

__device__ __forceinline__ void mma16816(float* c, const unsigned* a, unsigned b0, unsigned b1) {
    asm volatile(
        "mma.sync.aligned.m16n8k16.row.col.f32.bf16.bf16.f32 "
        "{%0,%1,%2,%3},{%4,%5,%6,%7},{%8,%9},{%0,%1,%2,%3};\n"
        : "+f"(c[0]), "+f"(c[1]), "+f"(c[2]), "+f"(c[3])
        : "r"(a[0]), "r"(a[1]), "r"(a[2]), "r"(a[3]), "r"(b0), "r"(b1));
}

__global__ void __launch_bounds__(256, 2) score_kernel(
    const float* __restrict__ x, const float* __restrict__ b1,
    const float* __restrict__ w2, const float* __restrict__ b2,
    int nrows, int ntiles)
{
    extern __shared__ unsigned char smem_raw[];
    __nv_bfloat16* whi = (__nv_bfloat16*)smem_raw;          // [128][136]
    __nv_bfloat16* wlo = whi + HD * WSTRIDE;                // [128][136]
    float* sb1 = (float*)(wlo + HD * WSTRIDE);
    float* sw2 = sb1 + HD;

    for (int idx = threadIdx.x; idx < HD * HD; idx += blockDim.x) {
        int n = idx >> 7, k = idx & 127;
        whi[n * WSTRIDE + k] = g_w1hi[idx];
        wlo[n * WSTRIDE + k] = g_w1lo[idx];
    }
    if (threadIdx.x < HD) {
        sb1[threadIdx.x] = b1[threadIdx.x];
        sw2[threadIdx.x] = w2[threadIdx.x];
    }
    __syncthreads();

    float bias2 = b2[0];
    int warp = threadIdx.x >> 5, lane = threadIdx.x & 31;
    int g = lane >> 2, t = lane & 3;

    for (int tile = blockIdx.x; tile < ntiles; tile += gridDim.x) {
        int rbase = tile * 128 + warp * 16;
        int r0 = rbase + g, r1 = rbase + g + 8;
        bool ok0 = r0 < nrows, ok1 = r1 < nrows;
        const float* xr0 = x + (size_t)r0 * HD;
        const float* xr1 = x + (size_t)r1 * HD;

        float acc[16][4];
        #pragma unroll
        for (int j = 0; j < 16; j++) { acc[j][0] = 0.f; acc[j][1] = 0.f; acc[j][2] = 0.f; acc[j][3] = 0.f; }

        #pragma unroll
        for (int k0 = 0; k0 < 8; k0++) {
            int c0 = k0 * 16 + 2 * t;
            unsigned ah[4], al[4];
            float2 p;
            p = ok0 ? *(const float2*)(xr0 + c0)     : make_float2(0.f, 0.f);
            ah[0] = split_pack(p, al[0]);
            p = ok1 ? *(const float2*)(xr1 + c0)     : make_float2(0.f, 0.f);
            ah[1] = split_pack(p, al[1]);
            p = ok0 ? *(const float2*)(xr0 + c0 + 8) : make_float2(0.f, 0.f);
            ah[2] = split_pack(p, al[2]);
            p = ok1 ? *(const float2*)(xr1 + c0 + 8) : make_float2(0.f, 0.f);
            ah[3] = split_pack(p, al[3]);

            #pragma unroll
            for (int j = 0; j < 16; j++) {
                const __nv_bfloat16* bh = whi + (j * 8 + g) * WSTRIDE + c0;
                const __nv_bfloat16* bl = wlo + (j * 8 + g) * WSTRIDE + c0;
                unsigned bh0 = *(const unsigned*)bh;
                unsigned bh1 = *(const unsigned*)(bh + 8);
                unsigned bl0 = *(const unsigned*)bl;
                unsigned bl1 = *(const unsigned*)(bl + 8);
                mma16816(acc[j], ah, bh0, bh1);   // hi*hi
                mma16816(acc[j], ah, bl0, bl1);   // hi*lo
                mma16816(acc[j], al, bh0, bh1);   // lo*hi
            }
        }

        // epilogue: tanh + dot(w2), reduce across the 4 lanes of each row-group
        float p0 = 0.f, p1 = 0.f;
        #pragma unroll
        for (int j = 0; j < 16; j++) {
            int col0 = j * 8 + 2 * t;
            p0 += tanhf(acc[j][0] + sb1[col0])     * sw2[col0];
            p0 += tanhf(acc[j][1] + sb1[col0 + 1]) * sw2[col0 + 1];
            p1 += tanhf(acc[j][2] + sb1[col0])     * sw2[col0];
            p1 += tanhf(acc[j][3] + sb1[col0 + 1]) * sw2[col0 + 1];
        }
        p0 += __shfl_xor_sync(0xffffffffu, p0, 1);
        p0 += __shfl_xor_sync(0xffffffffu, p0, 2);
        p1 += __shfl_xor_sync(0xffffffffu, p1, 1);
        p1 += __shfl_xor_sync(0xffffffffu, p1, 2);
        if (t == 0) {
            if (ok0) g_s[r0] = p0 + bias2;
            if (ok1) g_s[r1] = p1 + bias2;
        }
    }
}

// ---------------- K3: per-graph softmax + weighted pooling ----------------
__global__ void pool_kernel(const float* __restrict__ x, float* __restrict__ out, int G) {
    __shared__ float wsm[128];
    __shared__ float red[4];
    int gidx = blockIdx.x;
    int tid = threadIdx.x;
    int s0 = g_seg[gidx], s1 = g_seg[gidx + 1];

    // max
    float m = -INFINITY;
    for (int i = s0 + tid; i < s1; i += 128) m = fmaxf(m, g_s[i]);
    #pragma unroll
    for (int o = 16; o; o >>= 1) m = fmaxf(m, __shfl_xor_sync(0xffffffffu, m, o));
    if ((tid & 31) == 0) red[tid >> 5] = m;
    __syncthreads();
    m = fmaxf(fmaxf(red[0], red[1]), fmaxf(red[2], red[3]));
    __syncthreads();

    // denom
    float ds = 0.f;
    for (int i = s0 + tid; i < s1; i += 128) ds += __expf(g_s[i] - m);
    #pragma unroll
    for (int o = 16; o; o >>= 1) ds += __shfl_xor_sync(0xffffffffu, ds, o);
    if ((tid & 31) == 0) red[tid >> 5] = ds;
    __syncthreads();
    float denom = red[0] + red[1] + red[2] + red[3];
    float inv = (s1 > s0 && denom > 0.f) ? (1.f / denom) : 0.f;

    // weighted pooling: thread tid owns column tid
    float acc = 0.f;
    for (int base = s0; base < s1; base += 128) {
        int i = base + tid;
        __syncthreads();
        wsm[tid] = (i < s1) ? (__expf(g_s[i] - m) * inv) : 0.f;
        __syncthreads();
        int cnt = min(128, s1 - base);
        const float* xp = x + (size_t)base * HD + tid;
        int j = 0;
        for (; j + 4 <= cnt; j += 4) {
            float a0 = xp[(size_t)(j + 0) * HD];
            float a1 = xp[(size_t)(j + 1) * HD];
            float a2 = xp[(size_t)(j + 2) * HD];
            float a3 = xp[(size_t)(j + 3) * HD];
            acc += wsm[j] * a0;
            acc += wsm[j + 1] * a1;
            acc += wsm[j + 2] * a2;
            acc += wsm[j + 3] * a3;
        }
        for (; j < cnt; j++) acc += wsm[j] * xp[(size_t)j * HD];
    }
    out[(size_t)gidx * HD + tid] = acc;
}

// ---------------- launch ----------------
extern "C" void kernel_launch(void* const* d_in, const int* in_sizes, int n_in,
                              void* d_out, int out_size) {
    const float* x  = (const float*)d_in[0];
    const void*  batch = d_in[1];
    const float* w1 = (const float*)d_in[2];
    const float* b1 = (const float*)d_in[3];
    const float* w2 = (const float*)d_in[4];
    const float* b2 = (const float*)d_in[5];
    float* out = (float*)d_out;

    int N = in_sizes[1];           // rows
    int G = out_size / HD;         // graphs
    int ntiles = (N + 127) / 128;

    const int SMEM = 2 * HD * WSTRIDE * (int)sizeof(__nv_bfloat16) + 2 * HD * (int)sizeof(float);
    cudaFuncSetAttribute(score_kernel, cudaFuncAttributeMaxDynamicSharedMemorySize, SMEM);

    prep_w1_kernel<<<(HD * HD + 255) / 256, 256>>>(w1);
    score_kernel<<<304, 256, SMEM>>>(x, b1, w2, b2, N, ntiles);
    seg_kernel<<<(G + 1 + 255) / 256, 256>>>(batch, N, G);
    pool_kernel<<<G, 128>>>(x, out, G);
}

// round 17
// speedup vs baseline: 1.0664x; 1.0652x over previous
#include <cuda_runtime.h>
#include <cuda_bf16.h>
#include <math.h>

#define HD 128
#define NMAX 1048576
#define GMAX 4608

// ---------------- scratch (device globals; no allocation allowed) ----------------
__device__ float    g_s[NMAX];          // per-row attention logits
__device__ int      g_seg[GMAX + 1];    // segment boundaries
__device__ unsigned g_wfrag[16384];     // w1^T in tf32, mma-fragment order

// ---------------- helpers ----------------
__device__ __forceinline__ unsigned f2tf32(float f) {
    unsigned u;
    asm("cvt.rna.tf32.f32 %0, %1;" : "=r"(u) : "f"(f));
    return u;
}

__device__ __forceinline__ void mma1688tf32(float* c,
    unsigned a0, unsigned a1, unsigned a2, unsigned a3,
    unsigned b0, unsigned b1)
{
    asm volatile(
        "mma.sync.aligned.m16n8k8.row.col.f32.tf32.tf32.f32 "
        "{%0,%1,%2,%3},{%4,%5,%6,%7},{%8,%9},{%0,%1,%2,%3};\n"
        : "+f"(c[0]), "+f"(c[1]), "+f"(c[2]), "+f"(c[3])
        : "r"(a0), "r"(a1), "r"(a2), "r"(a3), "r"(b0), "r"(b1));
}

// ---------------- K0: w1 -> tf32 fragment-order layout ----------------
// For mma.m16n8k8 (row.col), lane holds B elements:
//   b0:(k=tig,   n=lane/4)  b1:(k=tig+4, n=lane/4)   [tig = lane%4]
// Per (j = n-block of 8, k0 = k-block of 16) we pack the 4 regs needed by
// the two k8 mmas contiguously so the kernel does one LDS.128 per (j,k0).
// idx = ((j*8 + k0)*32 + lane)*4 + q,  k = k0*16 + tig + 4*q,  n = j*8 + lane/4
__global__ void prep_wfrag_kernel(const float* __restrict__ w1) {
    int idx = blockIdx.x * blockDim.x + threadIdx.x;
    if (idx >= 16384) return;
    int q    = idx & 3;
    int lane = (idx >> 2) & 31;
    int k0   = (idx >> 7) & 7;
    int j    = idx >> 10;
    int n = j * 8 + (lane >> 2);
    int k = k0 * 16 + (lane & 3) + 4 * q;
    g_wfrag[idx] = f2tf32(w1[k * HD + n]);   // w1 is [k][n] row-major
}

// ---------------- K2: segment boundaries (binary search over sorted batch) ----------------
__global__ void seg_kernel(const void* __restrict__ batch_raw, int n, int G) {
    const int* v32 = (const int*)batch_raw;
    bool is64 = (v32[(n / 2) | 1] == 0) && (v32[(n / 4) | 1] == 0) && (v32[(n / 3) | 1] == 0);
    int gg = blockIdx.x * blockDim.x + threadIdx.x;
    if (gg > G) return;
    long long key = (long long)gg;
    int lo = 0, hi = n;
    const long long* v64 = (const long long*)batch_raw;
    while (lo < hi) {
        int mid = (lo + hi) >> 1;
        long long bv = is64 ? v64[mid] : (long long)v32[mid];
        if (bv < key) lo = mid + 1; else hi = mid;
    }
    g_seg[gg] = lo;
}

// ---------------- K1: score kernel (tf32 single-pass tensor-core MLP) ----------------
__global__ void __launch_bounds__(256, 2) score_kernel(
    const float* __restrict__ x, const float* __restrict__ b1,
    const float* __restrict__ w2, const float* __restrict__ b2,
    int nrows, int ntiles)
{
    extern __shared__ unsigned char smem_raw[];
    uint4* wf  = (uint4*)smem_raw;             // 4096 x uint4 (64KB), frag order
    float* sb1 = (float*)(wf + 4096);
    float* sw2 = sb1 + HD;

    const uint4* gwf = (const uint4*)g_wfrag;
    for (int idx = threadIdx.x; idx < 4096; idx += blockDim.x)
        wf[idx] = gwf[idx];
    if (threadIdx.x < HD) {
        sb1[threadIdx.x] = b1[threadIdx.x];
        sw2[threadIdx.x] = w2[threadIdx.x];
    }
    __syncthreads();

    float bias2 = b2[0];
    int warp = threadIdx.x >> 5, lane = threadIdx.x & 31;
    int g = lane >> 2, t = lane & 3;

    for (int tile = blockIdx.x; tile < ntiles; tile += gridDim.x) {
        int rbase = tile * 128 + warp * 16;
        int r0 = rbase + g, r1 = r0 + 8;
        bool ok0 = r0 < nrows, ok1 = r1 < nrows;
        const float* xr0 = x + (size_t)r0 * HD;
        const float* xr1 = x + (size_t)r1 * HD;

        float acc[16][4];
        #pragma unroll
        for (int j = 0; j < 16; j++) {
            acc[j][0] = 0.f; acc[j][1] = 0.f; acc[j][2] = 0.f; acc[j][3] = 0.f;
        }

        #pragma unroll
        for (int k0 = 0; k0 < 8; k0++) {
            int c = k0 * 16 + t;
            // A fragments for the two k8 mmas of this k16 chunk
            unsigned a0 = f2tf32(ok0 ? __ldg(xr0 + c)      : 0.f);
            unsigned a1 = f2tf32(ok1 ? __ldg(xr1 + c)      : 0.f);
            unsigned a2 = f2tf32(ok0 ? __ldg(xr0 + c + 4)  : 0.f);
            unsigned a3 = f2tf32(ok1 ? __ldg(xr1 + c + 4)  : 0.f);
            unsigned a4 = f2tf32(ok0 ? __ldg(xr0 + c + 8)  : 0.f);
            unsigned a5 = f2tf32(ok1 ? __ldg(xr1 + c + 8)  : 0.f);
            unsigned a6 = f2tf32(ok0 ? __ldg(xr0 + c + 12) : 0.f);
            unsigned a7 = f2tf32(ok1 ? __ldg(xr1 + c + 12) : 0.f);

            #pragma unroll
            for (int j = 0; j < 16; j++) {
                uint4 b = wf[(j * 8 + k0) * 32 + lane];
                mma1688tf32(acc[j], a0, a1, a2, a3, b.x, b.y);
                mma1688tf32(acc[j], a4, a5, a6, a7, b.z, b.w);
            }
        }

        // epilogue: tanh + dot(w2), reduce across the 4 lanes of each row-group
        float p0 = 0.f, p1 = 0.f;
        #pragma unroll
        for (int j = 0; j < 16; j++) {
            int col0 = j * 8 + 2 * t;
            p0 += tanhf(acc[j][0] + sb1[col0])     * sw2[col0];
            p0 += tanhf(acc[j][1] + sb1[col0 + 1]) * sw2[col0 + 1];
            p1 += tanhf(acc[j][2] + sb1[col0])     * sw2[col0];
            p1 += tanhf(acc[j][3] + sb1[col0 + 1]) * sw2[col0 + 1];
        }
        p0 += __shfl_xor_sync(0xffffffffu, p0, 1);
        p0 += __shfl_xor_sync(0xffffffffu, p0, 2);
        p1 += __shfl_xor_sync(0xffffffffu, p1, 1);
        p1 += __shfl_xor_sync(0xffffffffu, p1, 2);
        if (t == 0) {
            if (ok0) g_s[r0] = p0 + bias2;
            if (ok1) g_s[r1] = p1 + bias2;
        }
    }
}

// ---------------- K3: per-graph softmax + weighted pooling (float4 path) ----------------
__global__ void pool_kernel(const float* __restrict__ x, float* __restrict__ out, int G) {
    __shared__ float red[4];
    __shared__ float accsm[4][HD];
    int gidx = blockIdx.x;
    int tid = threadIdx.x;
    int s0 = g_seg[gidx], s1 = g_seg[gidx + 1];

    // max
    float m = -INFINITY;
    for (int i = s0 + tid; i < s1; i += 128) m = fmaxf(m, g_s[i]);
    #pragma unroll
    for (int o = 16; o; o >>= 1) m = fmaxf(m, __shfl_xor_sync(0xffffffffu, m, o));
    if ((tid & 31) == 0) red[tid >> 5] = m;
    __syncthreads();
    m = fmaxf(fmaxf(red[0], red[1]), fmaxf(red[2], red[3]));
    __syncthreads();

    // denom
    float ds = 0.f;
    for (int i = s0 + tid; i < s1; i += 128) ds += __expf(g_s[i] - m);
    #pragma unroll
    for (int o = 16; o; o >>= 1) ds += __shfl_xor_sync(0xffffffffu, ds, o);
    if ((tid & 31) == 0) red[tid >> 5] = ds;
    __syncthreads();
    float denom = red[0] + red[1] + red[2] + red[3];
    float inv = (s1 > s0 && denom > 0.f) ? (1.f / denom) : 0.f;

    // weighted pooling: 4 row-groups x 32 lanes; lane owns a float4 of columns
    int quad = tid >> 5, lane = tid & 31;
    const float4* xv = (const float4*)x;   // row i -> xv[i*32 + lane]
    float4 acc0 = make_float4(0.f, 0.f, 0.f, 0.f);
    float4 acc1 = make_float4(0.f, 0.f, 0.f, 0.f);

    int j = s0 + quad;
    for (; j + 4 < s1; j += 8) {
        float w0 = __expf(g_s[j] - m) * inv;
        float w1 = __expf(g_s[j + 4] - m) * inv;
        float4 v0 = xv[(size_t)j * 32 + lane];
        float4 v1 = xv[(size_t)(j + 4) * 32 + lane];
        acc0.x += w0 * v0.x; acc0.y += w0 * v0.y; acc0.z += w0 * v0.z; acc0.w += w0 * v0.w;
        acc1.x += w1 * v1.x; acc1.y += w1 * v1.y; acc1.z += w1 * v1.z; acc1.w += w1 * v1.w;
    }
    if (j < s1) {
        float w0 = __expf(g_s[j] - m) * inv;
        float4 v0 = xv[(size_t)j * 32 + lane];
        acc0.x += w0 * v0.x; acc0.y += w0 * v0.y; acc0.z += w0 * v0.z; acc0.w += w0 * v0.w;
    }
    acc0.x += acc1.x; acc0.y += acc1.y; acc0.z += acc1.z; acc0.w += acc1.w;

    ((float4*)accsm[quad])[lane] = acc0;
    __syncthreads();
    float r = accsm[0][tid] + accsm[1][tid] + accsm[2][tid] + accsm[3][tid];
    out[(size_t)gidx * HD + tid] = r;
}

// ---------------- launch ----------------
extern "C" void kernel_launch(void* const* d_in, const int* in_sizes, int n_in,
                              void* d_out, int out_size) {
    const float* x  = (const float*)d_in[0];
    const void*  batch = d_in[1];
    const float* w1 = (const float*)d_in[2];
    const float* b1 = (const float*)d_in[3];
    const float* w2 = (const float*)d_in[4];
    const float* b2 = (const float*)d_in[5];
    float* out = (float*)d_out;

    int N = in_sizes[1];           // rows
    int G = out_size / HD;         // graphs
    int ntiles = (N + 127) / 128;

    const int SMEM = 4096 * 16 + 2 * HD * (int)sizeof(float);   // 66560
    cudaFuncSetAttribute(score_kernel, cudaFuncAttributeMaxDynamicSharedMemorySize, SMEM);

    prep_wfrag_kernel<<<64, 256>>>(w1);
    score_kernel<<<304, 256, SMEM>>>(x, b1, w2, b2, N, ntiles);
    seg_kernel<<<(G + 1 + 255) / 256, 256>>>(batch, N, G);
    pool_kernel<<<G, 128>>>(x, out, G);
}